// round 1
// baseline (speedup 1.0000x reference)
#include <cuda_runtime.h>

// Problem dims (fixed by the dataset)
#define B_ 4096
#define I_ 512
#define H_ 1024
#define G4 (4 * H_)   // 4096

// Scratch: gates pre-activation [B, 4H] and C_ST = tanh(cx@W+b) [B, H]
__device__ float g_gates[(size_t)B_ * G4];
__device__ float g_cst[(size_t)B_ * H_];

// ---------------- SGEMM tiling ----------------
#define BM 128
#define BN 128
#define BK 16
#define PAD 4
#define LDSROW (BM + PAD)   // padded shared row stride (132 floats = 528B, 16B-aligned)

// C[M=4096, N=4096] = A1[4096,512] @ W1[4096,512]^T + A2[4096,1024] @ W2[4096,1024]^T
//                     + bias_ih[n] + bias_hh[n]
// Both GEMMs are "NT": A and W are K-contiguous -> float4 global loads, transpose into smem.
__global__ __launch_bounds__(256) void gates_gemm_kernel(
    const float* __restrict__ A1, const float* __restrict__ W1,
    const float* __restrict__ A2, const float* __restrict__ W2,
    const float* __restrict__ b1, const float* __restrict__ b2,
    float* __restrict__ C)
{
    __shared__ float As[BK][LDSROW];
    __shared__ float Bs[BK][LDSROW];

    const int t  = threadIdx.x;
    const int tx = t & 15;       // 0..15 -> N sub-tile
    const int ty = t >> 4;       // 0..15 -> M sub-tile
    const int mBase = blockIdx.y * BM;
    const int nBase = blockIdx.x * BN;

    float acc[8][8];
    #pragma unroll
    for (int i = 0; i < 8; ++i)
        #pragma unroll
        for (int j = 0; j < 8; ++j) acc[i][j] = 0.0f;

    #pragma unroll
    for (int seg = 0; seg < 2; ++seg) {
        const float* A = seg ? A2 : A1;
        const float* W = seg ? W2 : W1;
        const int K = seg ? H_ : I_;

        for (int k0 = 0; k0 < K; k0 += BK) {
            // Load A tile (BM x BK), transpose into As[BK][BM]
            #pragma unroll
            for (int i = 0; i < 2; ++i) {
                int li  = t + i * 256;           // 0..511
                int row = li >> 2;               // 0..127
                int c4  = (li & 3) * 4;          // 0,4,8,12
                float4 v = *(const float4*)&A[(size_t)(mBase + row) * K + k0 + c4];
                As[c4 + 0][row] = v.x; As[c4 + 1][row] = v.y;
                As[c4 + 2][row] = v.z; As[c4 + 3][row] = v.w;
            }
            // Load W tile (BN x BK), transpose into Bs[BK][BN]
            #pragma unroll
            for (int i = 0; i < 2; ++i) {
                int li  = t + i * 256;
                int row = li >> 2;
                int c4  = (li & 3) * 4;
                float4 v = *(const float4*)&W[(size_t)(nBase + row) * K + k0 + c4];
                Bs[c4 + 0][row] = v.x; Bs[c4 + 1][row] = v.y;
                Bs[c4 + 2][row] = v.z; Bs[c4 + 3][row] = v.w;
            }
            __syncthreads();

            #pragma unroll
            for (int k = 0; k < BK; ++k) {
                float a[8], b[8];
                float4 a0 = *(const float4*)&As[k][ty * 8];
                float4 a1 = *(const float4*)&As[k][ty * 8 + 4];
                float4 bb0 = *(const float4*)&Bs[k][tx * 8];
                float4 bb1 = *(const float4*)&Bs[k][tx * 8 + 4];
                a[0]=a0.x; a[1]=a0.y; a[2]=a0.z; a[3]=a0.w;
                a[4]=a1.x; a[5]=a1.y; a[6]=a1.z; a[7]=a1.w;
                b[0]=bb0.x; b[1]=bb0.y; b[2]=bb0.z; b[3]=bb0.w;
                b[4]=bb1.x; b[5]=bb1.y; b[6]=bb1.z; b[7]=bb1.w;
                #pragma unroll
                for (int i = 0; i < 8; ++i)
                    #pragma unroll
                    for (int j = 0; j < 8; ++j)
                        acc[i][j] = fmaf(a[i], b[j], acc[i][j]);
            }
            __syncthreads();
        }
    }

    // Epilogue: add biases, write out (vectorized)
    const int n0 = nBase + tx * 8;
    float bv[8];
    #pragma unroll
    for (int j = 0; j < 8; ++j) bv[j] = b1[n0 + j] + b2[n0 + j];

    #pragma unroll
    for (int i = 0; i < 8; ++i) {
        const size_t rowOff = (size_t)(mBase + ty * 8 + i) * G4 + n0;
        float4 o0, o1;
        o0.x = acc[i][0] + bv[0]; o0.y = acc[i][1] + bv[1];
        o0.z = acc[i][2] + bv[2]; o0.w = acc[i][3] + bv[3];
        o1.x = acc[i][4] + bv[4]; o1.y = acc[i][5] + bv[5];
        o1.z = acc[i][6] + bv[6]; o1.w = acc[i][7] + bv[7];
        *(float4*)&C[rowOff]     = o0;
        *(float4*)&C[rowOff + 4] = o1;
    }
}

// C_ST[B, H] = tanh(cx[B,H] @ W[H,H] + bias[n])   (NN layout)
__global__ __launch_bounds__(256) void cst_gemm_kernel(
    const float* __restrict__ A,     // cx
    const float* __restrict__ W,     // W_decomp row-major [H, H]
    const float* __restrict__ bias,  // b_decomp
    float* __restrict__ C)           // g_cst
{
    __shared__ float As[BK][LDSROW];
    __shared__ float Bs[BK][LDSROW];

    const int t  = threadIdx.x;
    const int tx = t & 15;
    const int ty = t >> 4;
    const int mBase = blockIdx.y * BM;
    const int nBase = blockIdx.x * BN;

    float acc[8][8];
    #pragma unroll
    for (int i = 0; i < 8; ++i)
        #pragma unroll
        for (int j = 0; j < 8; ++j) acc[i][j] = 0.0f;

    for (int k0 = 0; k0 < H_; k0 += BK) {
        // A tile (BM x BK) transposed
        #pragma unroll
        for (int i = 0; i < 2; ++i) {
            int li  = t + i * 256;
            int row = li >> 2;
            int c4  = (li & 3) * 4;
            float4 v = *(const float4*)&A[(size_t)(mBase + row) * H_ + k0 + c4];
            As[c4 + 0][row] = v.x; As[c4 + 1][row] = v.y;
            As[c4 + 2][row] = v.z; As[c4 + 3][row] = v.w;
        }
        // W tile (BK x BN), N-contiguous -> direct float4 store
        #pragma unroll
        for (int i = 0; i < 2; ++i) {
            int li  = t + i * 256;
            int kr  = li >> 5;            // 0..15
            int nc4 = (li & 31) * 4;      // 0..124
            float4 v = *(const float4*)&W[(size_t)(k0 + kr) * H_ + nBase + nc4];
            *(float4*)&Bs[kr][nc4] = v;
        }
        __syncthreads();

        #pragma unroll
        for (int k = 0; k < BK; ++k) {
            float a[8], b[8];
            float4 a0 = *(const float4*)&As[k][ty * 8];
            float4 a1 = *(const float4*)&As[k][ty * 8 + 4];
            float4 bb0 = *(const float4*)&Bs[k][tx * 8];
            float4 bb1 = *(const float4*)&Bs[k][tx * 8 + 4];
            a[0]=a0.x; a[1]=a0.y; a[2]=a0.z; a[3]=a0.w;
            a[4]=a1.x; a[5]=a1.y; a[6]=a1.z; a[7]=a1.w;
            b[0]=bb0.x; b[1]=bb0.y; b[2]=bb0.z; b[3]=bb0.w;
            b[4]=bb1.x; b[5]=bb1.y; b[6]=bb1.z; b[7]=bb1.w;
            #pragma unroll
            for (int i = 0; i < 8; ++i)
                #pragma unroll
                for (int j = 0; j < 8; ++j)
                    acc[i][j] = fmaf(a[i], b[j], acc[i][j]);
        }
        __syncthreads();
    }

    const int n0 = nBase + tx * 8;
    float bv[8];
    #pragma unroll
    for (int j = 0; j < 8; ++j) bv[j] = bias[n0 + j];

    #pragma unroll
    for (int i = 0; i < 8; ++i) {
        const size_t rowOff = (size_t)(mBase + ty * 8 + i) * H_ + n0;
        float4 o0, o1;
        o0.x = tanhf(acc[i][0] + bv[0]); o0.y = tanhf(acc[i][1] + bv[1]);
        o0.z = tanhf(acc[i][2] + bv[2]); o0.w = tanhf(acc[i][3] + bv[3]);
        o1.x = tanhf(acc[i][4] + bv[4]); o1.y = tanhf(acc[i][5] + bv[5]);
        o1.z = tanhf(acc[i][6] + bv[6]); o1.w = tanhf(acc[i][7] + bv[7]);
        *(float4*)&C[rowOff]     = o0;
        *(float4*)&C[rowOff + 4] = o1;
    }
}

__device__ __forceinline__ float sigmoidf_(float x) {
    return 1.0f / (1.0f + expf(-x));
}

// Elementwise T-LSTM epilogue: out[0:B*H] = hy, out[B*H:2*B*H] = cy
__global__ __launch_bounds__(256) void tlstm_epilogue_kernel(
    const float* __restrict__ tvec,  // [B,1]
    const float* __restrict__ cx,    // [B,H]
    float* __restrict__ out)
{
    const int idx = blockIdx.x * blockDim.x + threadIdx.x;  // < B*H
    const int b = idx >> 10;         // / H_
    const float tb = tvec[b];
    const float T = (tb != 0.0f) ? (1.0f / tb) : 0.0f;

    const float* grow = g_gates + (size_t)b * G4 + (idx & (H_ - 1));
    const float ig = grow[0];
    const float fg = grow[H_];
    const float cg = grow[2 * H_];
    const float og = grow[3 * H_];

    const float cst = g_cst[idx];
    const float c   = cx[idx];
    const float cadj = c - cst + T * cst;

    const float i_s = sigmoidf_(ig);
    const float f_s = sigmoidf_(fg);
    const float g_t = tanhf(cg);
    const float o_s = sigmoidf_(og);

    const float cy = f_s * cadj + i_s * g_t;
    const float hy = o_s * tanhf(cy);

    out[idx] = hy;
    out[(size_t)B_ * H_ + idx] = cy;
}

extern "C" void kernel_launch(void* const* d_in, const int* in_sizes, int n_in,
                              void* d_out, int out_size) {
    const float* input     = (const float*)d_in[0];  // [B, I]
    const float* t         = (const float*)d_in[1];  // [B, 1]
    const float* hx        = (const float*)d_in[2];  // [B, H]
    const float* cx        = (const float*)d_in[3];  // [B, H]
    const float* weight_ih = (const float*)d_in[4];  // [4H, I]
    const float* weight_hh = (const float*)d_in[5];  // [4H, H]
    const float* bias_ih   = (const float*)d_in[6];  // [4H]
    const float* bias_hh   = (const float*)d_in[7];  // [4H]
    const float* W_decomp  = (const float*)d_in[8];  // [H, H]
    const float* b_decomp  = (const float*)d_in[9];  // [H]
    float* out = (float*)d_out;                      // [2, B, H] (hy, cy)

    float* gates_ptr = nullptr;
    float* cst_ptr = nullptr;
    cudaGetSymbolAddress((void**)&gates_ptr, g_gates);
    cudaGetSymbolAddress((void**)&cst_ptr, g_cst);

    // Gates GEMM: [4096, 4096] output, 128x128 tiles
    {
        dim3 grid(G4 / BN, B_ / BM);
        gates_gemm_kernel<<<grid, 256>>>(input, weight_ih, hx, weight_hh,
                                         bias_ih, bias_hh, gates_ptr);
    }
    // C_ST GEMM: [4096, 1024] output
    {
        dim3 grid(H_ / BN, B_ / BM);
        cst_gemm_kernel<<<grid, 256>>>(cx, W_decomp, b_decomp, cst_ptr);
    }
    // Epilogue
    {
        const int n = B_ * H_;
        tlstm_epilogue_kernel<<<n / 256, 256>>>(t, cx, out);
    }
}

// round 3
// speedup vs baseline: 2.0402x; 2.0402x over previous
#include <cuda_runtime.h>
#include <cuda_bf16.h>
#include <cstdint>

// ---------------- problem dims ----------------
#define B_ 4096
#define I_ 512
#define H_ 1024
#define G4 4096
#define KG 1536   // gates GEMM K (512 + 1024)
#define KC 1024   // cst GEMM K

// ---------------- scratch (device globals; no allocs allowed) ----------------
__device__ float g_gates[(size_t)B_ * G4];
__device__ float g_cst[(size_t)B_ * H_];
__device__ float g_bias[G4];
__device__ __nv_bfloat16 gA_hi[(size_t)B_ * KG];
__device__ __nv_bfloat16 gA_lo[(size_t)B_ * KG];
__device__ __nv_bfloat16 gW_hi[(size_t)G4 * KG];
__device__ __nv_bfloat16 gW_lo[(size_t)G4 * KG];
__device__ __nv_bfloat16 gCx_hi[(size_t)B_ * KC];
__device__ __nv_bfloat16 gCx_lo[(size_t)B_ * KC];
__device__ __nv_bfloat16 gWd_hi[(size_t)H_ * KC];
__device__ __nv_bfloat16 gWd_lo[(size_t)H_ * KC];

// ---------------- low-level helpers ----------------
__device__ __forceinline__ uint32_t smem_u32(const void* p) {
    uint32_t a;
    asm("{ .reg .u64 t; cvta.to.shared.u64 t, %1; cvt.u32.u64 %0, t; }" : "=r"(a) : "l"(p));
    return a;
}
__device__ __forceinline__ void cp16(uint32_t dst, const void* src) {
    asm volatile("cp.async.cg.shared.global [%0], [%1], 16;" :: "r"(dst), "l"(src));
}
#define CP_COMMIT() asm volatile("cp.async.commit_group;" ::: "memory")
#define CP_WAIT1()  asm volatile("cp.async.wait_group 1;" ::: "memory")

__device__ __forceinline__ void ldm_x4(uint32_t& r0, uint32_t& r1, uint32_t& r2, uint32_t& r3,
                                       uint32_t addr) {
    asm volatile("ldmatrix.sync.aligned.m8n8.x4.shared.b16 {%0,%1,%2,%3}, [%4];"
                 : "=r"(r0), "=r"(r1), "=r"(r2), "=r"(r3) : "r"(addr));
}
__device__ __forceinline__ void mma_bf16(float* c, const uint32_t* a, const uint32_t* b) {
    asm volatile(
        "mma.sync.aligned.m16n8k16.row.col.f32.bf16.bf16.f32 "
        "{%0,%1,%2,%3}, {%4,%5,%6,%7}, {%8,%9}, {%0,%1,%2,%3};"
        : "+f"(c[0]), "+f"(c[1]), "+f"(c[2]), "+f"(c[3])
        : "r"(a[0]), "r"(a[1]), "r"(a[2]), "r"(a[3]), "r"(b[0]), "r"(b[1]));
}

// ---------------- GEMM tiling ----------------
// CTA tile 128x128, BK=32 (bf16). 8 warps: warp_m = wid&3 (32 rows), warp_n = wid>>2 (64 cols).
// smem rows padded to 80 bytes (32 bf16 = 64B data + 16B pad) -> conflict-free ldmatrix.
#define BKE 32               // K elements per chunk
#define ROWB 80              // smem bytes per tile row
#define TILEB (128 * ROWB)   // 10240
#define OFF_AH 0
#define OFF_AL TILEB
#define OFF_BH (2 * TILEB)
#define OFF_BL (3 * TILEB)
#define STAGEB (4 * TILEB)   // 40960
#define SMEM_DYN (2 * STAGEB)

// One stage of loads: 8 cp.async (16B) per thread (256 threads).
__device__ __forceinline__ void load_stage(
    uint32_t sb,
    const __nv_bfloat16* __restrict__ Ahi, const __nv_bfloat16* __restrict__ Alo,
    const __nv_bfloat16* __restrict__ Bhi, const __nv_bfloat16* __restrict__ Blo,
    int mBase, int nBase, int k0, int Ktot, int tid)
{
    #pragma unroll
    for (int i = 0; i < 2; ++i) {
        const int id  = tid + i * 256;      // 0..511
        const int row = id >> 2;            // 0..127
        const int c   = id & 3;             // 16B chunk within 64B row
        const uint32_t doff = row * ROWB + c * 16;
        const size_t aoff = (size_t)(mBase + row) * Ktot + k0 + c * 8;
        const size_t boff = (size_t)(nBase + row) * Ktot + k0 + c * 8;
        cp16(sb + OFF_AH + doff, Ahi + aoff);
        cp16(sb + OFF_AL + doff, Alo + aoff);
        cp16(sb + OFF_BH + doff, Bhi + boff);
        cp16(sb + OFF_BL + doff, Blo + boff);
    }
}

// act==0: C = D + bias[n]      act==1: C = tanh(D + bias[n])
__global__ __launch_bounds__(256) void tc_gemm_kernel(
    const __nv_bfloat16* __restrict__ Ahi, const __nv_bfloat16* __restrict__ Alo,
    const __nv_bfloat16* __restrict__ Bhi, const __nv_bfloat16* __restrict__ Blo,
    int Ktot, int ldC, const float* __restrict__ bias, int act,
    float* __restrict__ C)
{
    extern __shared__ char smem[];
    const uint32_t smem_base = smem_u32(smem);
    const int tid = threadIdx.x;
    const int wid = tid >> 5, lane = tid & 31;
    const int wm = (wid & 3) * 32;       // warp row offset in CTA tile
    const int wn = (wid >> 2) * 64;      // warp col offset in CTA tile
    const int mBase = blockIdx.y * 128, nBase = blockIdx.x * 128;

    float acc[2][8][4];
    #pragma unroll
    for (int i = 0; i < 2; ++i)
        #pragma unroll
        for (int j = 0; j < 8; ++j)
            #pragma unroll
            for (int q = 0; q < 4; ++q) acc[i][j][q] = 0.0f;

    const int nchunks = Ktot / BKE;

    // prologue: two stages in flight
    load_stage(smem_base, Ahi, Alo, Bhi, Blo, mBase, nBase, 0, Ktot, tid);
    CP_COMMIT();
    load_stage(smem_base + STAGEB, Ahi, Alo, Bhi, Blo, mBase, nBase, BKE, Ktot, tid);
    CP_COMMIT();

    // precomputed per-lane ldmatrix offsets (within a tile, before row base / kstep)
    // A: row = wm + mt*16 + (lane&15), colb = kstep*32 + (lane>=16 ? 16 : 0)
    // B: row = wn + nt16*16 + (lane&7) + (lane&16 ? 8 : 0), colb = kstep*32 + (lane&8 ? 16 : 0)
    const int aRow = wm + (lane & 15);
    const int aCol = (lane & 16);                       // 0 or 16 bytes
    const int bRow = wn + (lane & 7) + ((lane & 16) >> 1);
    const int bCol = (lane & 8) << 1;                   // 0 or 16 bytes

    for (int c = 0; c < nchunks; ++c) {
        const uint32_t sb = smem_base + (c & 1) * STAGEB;
        CP_WAIT1();
        __syncthreads();

        #pragma unroll
        for (int ks = 0; ks < 2; ++ks) {
            const int kb = ks * 32;
            uint32_t ah[2][4], al[2][4], bh[4][4], bl[4][4];
            #pragma unroll
            for (int mt = 0; mt < 2; ++mt) {
                const uint32_t ad = sb + (aRow + mt * 16) * ROWB + kb + aCol;
                ldm_x4(ah[mt][0], ah[mt][1], ah[mt][2], ah[mt][3], ad + OFF_AH);
                ldm_x4(al[mt][0], al[mt][1], al[mt][2], al[mt][3], ad + OFF_AL);
            }
            #pragma unroll
            for (int nt = 0; nt < 4; ++nt) {
                const uint32_t bd = sb + (bRow + nt * 16) * ROWB + kb + bCol;
                ldm_x4(bh[nt][0], bh[nt][1], bh[nt][2], bh[nt][3], bd + OFF_BH);
                ldm_x4(bl[nt][0], bl[nt][1], bl[nt][2], bl[nt][3], bd + OFF_BL);
            }
            // term 1: hi*hi   term 2: lo*hi   term 3: hi*lo
            #pragma unroll
            for (int mt = 0; mt < 2; ++mt)
                #pragma unroll
                for (int nt = 0; nt < 8; ++nt)
                    mma_bf16(acc[mt][nt], ah[mt], &bh[nt >> 1][(nt & 1) * 2]);
            #pragma unroll
            for (int mt = 0; mt < 2; ++mt)
                #pragma unroll
                for (int nt = 0; nt < 8; ++nt)
                    mma_bf16(acc[mt][nt], al[mt], &bh[nt >> 1][(nt & 1) * 2]);
            #pragma unroll
            for (int mt = 0; mt < 2; ++mt)
                #pragma unroll
                for (int nt = 0; nt < 8; ++nt)
                    mma_bf16(acc[mt][nt], ah[mt], &bl[nt >> 1][(nt & 1) * 2]);
        }

        __syncthreads();   // all warps done reading stage (c&1) before refill
        if (c + 2 < nchunks)
            load_stage(sb, Ahi, Alo, Bhi, Blo, mBase, nBase, (c + 2) * BKE, Ktot, tid);
        CP_COMMIT();       // keep group accounting aligned (empty groups ok)
    }

    // epilogue: fragment rows l/4 and l/4+8, cols (l%4)*2
    const int rq = lane >> 2, cq = (lane & 3) * 2;
    #pragma unroll
    for (int mt = 0; mt < 2; ++mt) {
        const int row0 = mBase + wm + mt * 16 + rq;
        #pragma unroll
        for (int nt = 0; nt < 8; ++nt) {
            const int col = nBase + wn + nt * 8 + cq;
            const float b0 = __ldg(&bias[col]), b1 = __ldg(&bias[col + 1]);
            float2 v0 = make_float2(acc[mt][nt][0] + b0, acc[mt][nt][1] + b1);
            float2 v1 = make_float2(acc[mt][nt][2] + b0, acc[mt][nt][3] + b1);
            if (act) {
                v0.x = tanhf(v0.x); v0.y = tanhf(v0.y);
                v1.x = tanhf(v1.x); v1.y = tanhf(v1.y);
            }
            *(float2*)&C[(size_t)row0 * ldC + col]       = v0;
            *(float2*)&C[(size_t)(row0 + 8) * ldC + col] = v1;
        }
    }
}

// ---------------- conversion / packing kernels ----------------
__device__ __forceinline__ void split_bf16(float v, __nv_bfloat16& h, __nv_bfloat16& l) {
    h = __float2bfloat16(v);
    l = __float2bfloat16(v - __bfloat162float(h));
}

__global__ __launch_bounds__(256) void pack_split2_kernel(
    const float* __restrict__ s1, const float* __restrict__ s2,
    __nv_bfloat16* __restrict__ hi, __nv_bfloat16* __restrict__ lo)
{
    const int row = blockIdx.x;
    #pragma unroll
    for (int i = 0; i < KG / 256; ++i) {
        const int k = threadIdx.x + i * 256;
        const float v = (k < I_) ? s1[(size_t)row * I_ + k]
                                 : s2[(size_t)row * H_ + (k - I_)];
        __nv_bfloat16 h, l; split_bf16(v, h, l);
        hi[(size_t)row * KG + k] = h;
        lo[(size_t)row * KG + k] = l;
    }
}

__global__ __launch_bounds__(256) void pack_split1_kernel(
    const float* __restrict__ src,
    __nv_bfloat16* __restrict__ hi, __nv_bfloat16* __restrict__ lo)
{
    const int row = blockIdx.x;
    #pragma unroll
    for (int i = 0; i < KC / 256; ++i) {
        const int k = threadIdx.x + i * 256;
        const float v = src[(size_t)row * KC + k];
        __nv_bfloat16 h, l; split_bf16(v, h, l);
        hi[(size_t)row * KC + k] = h;
        lo[(size_t)row * KC + k] = l;
    }
}

// out[n, k] = W[k, n]  (transpose + split), W is [H_, H_]
__global__ void pack_transpose_kernel(const float* __restrict__ W,
                                      __nv_bfloat16* __restrict__ hi,
                                      __nv_bfloat16* __restrict__ lo)
{
    __shared__ float tile[32][33];
    const int bx = blockIdx.x * 32, by = blockIdx.y * 32;
    const int tx = threadIdx.x, ty = threadIdx.y;   // 32 x 8
    #pragma unroll
    for (int i = 0; i < 32; i += 8)
        tile[ty + i][tx] = W[(size_t)(by + ty + i) * H_ + bx + tx];
    __syncthreads();
    #pragma unroll
    for (int i = 0; i < 32; i += 8) {
        const float v = tile[tx][ty + i];
        __nv_bfloat16 h, l; split_bf16(v, h, l);
        hi[(size_t)(bx + ty + i) * KC + by + tx] = h;
        lo[(size_t)(bx + ty + i) * KC + by + tx] = l;
    }
}

__global__ __launch_bounds__(256) void bias_kernel(const float* __restrict__ b1,
                                                   const float* __restrict__ b2,
                                                   float* __restrict__ out) {
    const int i = blockIdx.x * 256 + threadIdx.x;
    out[i] = b1[i] + b2[i];
}

// ---------------- T-LSTM elementwise epilogue ----------------
__device__ __forceinline__ float sigmoidf_(float x) { return 1.0f / (1.0f + expf(-x)); }

__global__ __launch_bounds__(256) void tlstm_epilogue_kernel(
    const float* __restrict__ tvec, const float* __restrict__ cx, float* __restrict__ out)
{
    const int idx = blockIdx.x * blockDim.x + threadIdx.x;  // < B*H
    const int b = idx >> 10;
    const float tb = tvec[b];
    const float T = (tb != 0.0f) ? (1.0f / tb) : 0.0f;

    const float* grow = g_gates + (size_t)b * G4 + (idx & (H_ - 1));
    const float ig = grow[0];
    const float fg = grow[H_];
    const float cg = grow[2 * H_];
    const float og = grow[3 * H_];

    const float cst  = g_cst[idx];
    const float c    = cx[idx];
    const float cadj = c - cst + T * cst;

    const float cy = sigmoidf_(fg) * cadj + sigmoidf_(ig) * tanhf(cg);
    const float hy = sigmoidf_(og) * tanhf(cy);

    out[idx] = hy;
    out[(size_t)B_ * H_ + idx] = cy;
}

// ---------------- launch ----------------
extern "C" void kernel_launch(void* const* d_in, const int* in_sizes, int n_in,
                              void* d_out, int out_size) {
    const float* input     = (const float*)d_in[0];
    const float* t         = (const float*)d_in[1];
    const float* hx        = (const float*)d_in[2];
    const float* cx        = (const float*)d_in[3];
    const float* weight_ih = (const float*)d_in[4];
    const float* weight_hh = (const float*)d_in[5];
    const float* bias_ih   = (const float*)d_in[6];
    const float* bias_hh   = (const float*)d_in[7];
    const float* W_decomp  = (const float*)d_in[8];
    const float* b_decomp  = (const float*)d_in[9];
    float* out = (float*)d_out;

    float *gates_p, *cst_p, *bias_p;
    __nv_bfloat16 *ah, *al, *wh, *wl, *ch, *cl, *dh, *dl;
    cudaGetSymbolAddress((void**)&gates_p, g_gates);
    cudaGetSymbolAddress((void**)&cst_p, g_cst);
    cudaGetSymbolAddress((void**)&bias_p, g_bias);
    cudaGetSymbolAddress((void**)&ah, gA_hi);
    cudaGetSymbolAddress((void**)&al, gA_lo);
    cudaGetSymbolAddress((void**)&wh, gW_hi);
    cudaGetSymbolAddress((void**)&wl, gW_lo);
    cudaGetSymbolAddress((void**)&ch, gCx_hi);
    cudaGetSymbolAddress((void**)&cl, gCx_lo);
    cudaGetSymbolAddress((void**)&dh, gWd_hi);
    cudaGetSymbolAddress((void**)&dl, gWd_lo);

    cudaFuncSetAttribute(tc_gemm_kernel, cudaFuncAttributeMaxDynamicSharedMemorySize, SMEM_DYN);

    // split/pack operands
    pack_split2_kernel<<<B_, 256>>>(input, hx, ah, al);
    pack_split2_kernel<<<G4, 256>>>(weight_ih, weight_hh, wh, wl);
    pack_split1_kernel<<<B_, 256>>>(cx, ch, cl);
    pack_transpose_kernel<<<dim3(H_ / 32, H_ / 32), dim3(32, 8)>>>(W_decomp, dh, dl);
    bias_kernel<<<G4 / 256, 256>>>(bias_ih, bias_hh, bias_p);

    // gates: [4096 x 4096] = A[4096,1536] @ W[4096,1536]^T + bias
    tc_gemm_kernel<<<dim3(G4 / 128, B_ / 128), 256, SMEM_DYN>>>(
        ah, al, wh, wl, KG, G4, bias_p, 0, gates_p);

    // C_ST: [4096 x 1024] = tanh(cx[4096,1024] @ Wd^T + b_decomp)
    tc_gemm_kernel<<<dim3(H_ / 128, B_ / 128), 256, SMEM_DYN>>>(
        ch, cl, dh, dl, KC, H_, b_decomp, 1, cst_p);

    // final elementwise T-LSTM
    tlstm_epilogue_kernel<<<(B_ * H_) / 256, 256>>>(t, cx, out);
}